// round 9
// baseline (speedup 1.0000x reference)
#include <cuda_runtime.h>
#include <cstdint>

// BidPrefix: row = [rates[0..299], market_price, bid]
//   cp1[j] = prod_{k<j} rates[k]
//   out[0:B]  = cp1[bid]            (bid in [0,300])
//   out[B:2B] = cp1[mp] - cp1[mp+1] (mp  in [0,299])
//
// Fully-resident grid (148 SMs x 16 blocks x 4 warps), each warp grid-strides
// over rows (~53 rows/warp) -> early-exit variance averages out, no retirement
// tail. Software pipeline: next row's tail + rounds 0,1 (unconditional,
// independent of everything) are issued BEFORE the current row's compute, so
// the warp always has loads in flight and the tail->predicated-load dependency
// never exposes DRAM latency.
// Interleaved ownership: lane t holds float2 chunks #(t+32k), k=0..4.
// cp1[x], x = 64q + r (warp-uniform):
//   m_t = c_q[t] * (2t<r ? vx_q : 1) * (2t+1<r ? vy_q : 1); butterfly-product.
// Rounds 2,3,4 predicated on maxf2 = max(bid-1,mp)>>1 (sector-granularity
// early exit); skipped chunks = (1,1), never referenced by any query.

static constexpr int ROW   = 302;
static constexpr int WARPS = 4;                 // 128-thread blocks
static constexpr int BLOCKS = 148 * 16;         // one resident wave
static constexpr unsigned FULL = 0xffffffffu;

struct QPre { float m, vx, vy; };

__device__ __forceinline__ QPre qpre(int x, int lane2,
                                     const float2& v0, const float2& v1,
                                     const float2& v2, const float2& v3,
                                     const float2& v4,
                                     float c1, float c2, float c3, float c4)
{
    const int q = x >> 6, r = x & 63;           // warp-uniform
    float cq = 1.0f;
    cq = (q == 1) ? c1 : cq;
    cq = (q == 2) ? c2 : cq;
    cq = (q == 3) ? c3 : cq;
    cq = (q == 4) ? c4 : cq;
    float vx = v0.x, vy = v0.y;
    vx = (q == 1) ? v1.x : vx;  vy = (q == 1) ? v1.y : vy;
    vx = (q == 2) ? v2.x : vx;  vy = (q == 2) ? v2.y : vy;
    vx = (q == 3) ? v3.x : vx;  vy = (q == 3) ? v3.y : vy;
    vx = (q == 4) ? v4.x : vx;  vy = (q == 4) ? v4.y : vy;
    float m = cq;
    m *= (lane2     < r) ? vx : 1.0f;
    m *= (lane2 + 1 < r) ? vy : 1.0f;
    return {m, vx, vy};
}

__global__ __launch_bounds__(128) void bidprefix_kernel(
    const float* __restrict__ in, float* __restrict__ out, int batch)
{
    const int lane   = threadIdx.x & 31;
    const int lane2  = 2 * lane;
    const int warp0  = blockIdx.x * WARPS + (threadIdx.x >> 5);
    const int stride = BLOCKS * WARPS;          // total warps in grid

    int row = warp0;
    // prologue: wave-1 for first row
    float2 t  = make_float2(0.f, 0.f);
    float2 u0 = t, u1 = t;
    if (row < batch) {
        const float2* R = reinterpret_cast<const float2*>(in + (size_t)row * ROW);
        t  = R[150];                            // floats [300]=mp, [301]=bid
        u0 = R[lane];
        u1 = R[lane + 32];
    }

    const float2 one = make_float2(1.0f, 1.0f);

    while (row < batch) {
        const float2* R = reinterpret_cast<const float2*>(in + (size_t)row * ROW);
        const int mp  = (int)t.x;               // 0..299
        const int bid = (int)t.y;               // 0..300
        const int mf  = max(bid - 1, mp) >> 1;  // last float2 chunk needed

        // wave-2: predicated early-exit loads for current row
        float2 v2 = one, v3 = one, v4 = one;
        if (lane +  64 <= mf) v2 = R[lane +  64];
        if (lane +  96 <= mf) v3 = R[lane +  96];
        if (lane + 128 <= mf) v4 = R[lane + 128];

        // prefetch next row's wave-1 (independent -> overlaps all compute below)
        const int nrow = row + stride;
        float2 nt = make_float2(0.f, 0.f), n0 = nt, n1 = nt;
        if (nrow < batch) {
            const float2* N = reinterpret_cast<const float2*>(in + (size_t)nrow * ROW);
            nt = N[150];
            n0 = N[lane];
            n1 = N[lane + 32];
        }

        // vertical chain: c_j = prod over rounds < j of (vx*vy)
        const float c1 = u0.x * u0.y;
        const float c2 = c1 * (u1.x * u1.y);
        const float c3 = c2 * (v2.x * v2.y);
        const float c4 = c3 * (v3.x * v3.y);

        const QPre sb = qpre(bid, lane2, u0, u1, v2, v3, v4, c1, c2, c3, c4);
        const QPre sm = qpre(mp,  lane2, u0, u1, v2, v3, v4, c1, c2, c3, c4);

        float m1 = sb.m, m2 = sm.m;
        #pragma unroll
        for (int off = 16; off; off >>= 1) {    // 2 chains pipeline SHFL latency
            const float w1 = __shfl_xor_sync(FULL, m1, off);
            const float w2 = __shfl_xor_sync(FULL, m2, off);
            m1 *= w1;
            m2 *= w2;
        }
        // m1 = cp1[bid], m2 = cp1[mp] in every lane

        // rates[mp]: reuse mp-query's selected round pair
        const float rsel = (mp & 1) ? sm.vy : sm.vx;
        const float rmp  = __shfl_sync(FULL, rsel, (mp & 63) >> 1);

        if (lane == 0) {
            out[row]         = m1;
            out[batch + row] = m2 - m2 * rmp;   // cp1[mp] - cp1[mp+1]
        }

        // rotate pipeline
        t = nt; u0 = n0; u1 = n1; row = nrow;
    }
}

extern "C" void kernel_launch(void* const* d_in, const int* in_sizes, int n_in,
                              void* d_out, int out_size)
{
    const float* in  = (const float*)d_in[0];
    float*       out = (float*)d_out;
    const int batch  = in_sizes[0] / ROW;       // 500000

    bidprefix_kernel<<<BLOCKS, 32 * WARPS>>>(in, out, batch);
}